// round 15
// baseline (speedup 1.0000x reference)
#include <cuda_runtime.h>
#include <cuda_bf16.h>
#include <math.h>
#include <stdint.h>

#define GG    4096
#define HH    512
#define FF    128
#define NPS   64
#define TWOH  1024
#define FOURH 2048

// ---------------- scratch (device globals; no allocation allowed) ----------
// NOTE: device-global symbols must only be referenced from DEVICE code.
__device__ float g_z[GG * FOURH];     // z = q_star @ R + bias
__device__ float g_c[GG * HH];        // LSTM cell state
__device__ float g_w[GG * FF];        // w_g = h_g @ MW^T
__device__ float g_w1[FF];
__device__ float g_bias2[FOURH];      // rb + h1 @ R_top
__device__ __nv_bfloat16 g_ahi[GG * TWOH];      // q_star hi (bf16)
__device__ __nv_bfloat16 g_alo[GG * TWOH];      // q_star lo (bf16)
__device__ __nv_bfloat16 g_bhi[FOURH * TWOH];   // R^T hi   [n][k]
__device__ __nv_bfloat16 g_blo[FOURH * TWOH];   // R^T lo   [n][k]
__device__ __nv_bfloat16 g_shi[GG * FF];        // s hi
__device__ __nv_bfloat16 g_slo[GG * FF];        // s lo
__device__ __nv_bfloat16 g_mwhi[FF * HH];       // MW hi    [f][k]
__device__ __nv_bfloat16 g_mwlo[FF * HH];
__device__ __nv_bfloat16 g_mthi[HH * FF];       // MW^T hi  [h][f]
__device__ __nv_bfloat16 g_mtlo[HH * FF];

__device__ __forceinline__ float hsig(float x) {
    return __saturatef(fmaf(0.2f, x, 0.5f));
}
__device__ __forceinline__ void mma16816(float* c, const uint32_t* a,
                                         const uint32_t* b) {
    asm volatile(
        "mma.sync.aligned.m16n8k16.row.col.f32.bf16.bf16.f32 "
        "{%0,%1,%2,%3}, {%4,%5,%6,%7}, {%8,%9}, {%0,%1,%2,%3};"
        : "+f"(c[0]), "+f"(c[1]), "+f"(c[2]), "+f"(c[3])
        : "r"(a[0]), "r"(a[1]), "r"(a[2]), "r"(a[3]), "r"(b[0]), "r"(b[1]));
}

// ---------------- k0_w1v2: w1[f] = sum_k MW[f,k]*h1[k], h1 inline ---------
__global__ __launch_bounds__(256) void k0_w1v2(const float* __restrict__ rb,
                                               const float* __restrict__ MW) {
    int warp = blockIdx.x * 8 + (threadIdx.x >> 5);   // 0..127
    int lane = threadIdx.x & 31;
    const float* row = MW + (size_t)warp * HH;
    float acc = 0.f;
#pragma unroll 4
    for (int k = lane; k < HH; k += 32) {
        float c  = hsig(rb[k]) * tanhf(rb[2 * HH + k]);
        float h1 = hsig(rb[3 * HH + k]) * tanhf(c);
        acc = fmaf(row[k], h1, acc);
    }
#pragma unroll
    for (int o = 16; o > 0; o >>= 1) acc += __shfl_xor_sync(0xffffffffu, acc, o);
    if (lane == 0) g_w1[warp] = acc;
}

// ---------------- k0_cb: fused c-init broadcast + bias2 single pass --------
// blocks [0,64):  bias2[n] = rb[n] + sum_k h1[k]*R[k][n]  (32 n per block)
// blocks [64, 64+8192): g_c[i] = c1(i mod 512), c1 computed inline from rb
__global__ __launch_bounds__(256) void k0_cb(const float* __restrict__ R,
                                             const float* __restrict__ rb) {
    int bid = blockIdx.x;
    int tid = threadIdx.x;
    if (bid < 64) {
        __shared__ float h1s[HH];
        __shared__ float part[8][32];
        int lane = tid & 31, warp = tid >> 5;
        for (int k = tid; k < HH; k += 256) {
            float c = hsig(rb[k]) * tanhf(rb[2 * HH + k]);
            h1s[k] = hsig(rb[3 * HH + k]) * tanhf(c);
        }
        __syncthreads();
        int n  = bid * 32 + lane;
        int ko = warp * 64;
        float acc = 0.f;
#pragma unroll 8
        for (int kk = 0; kk < 64; kk++)
            acc = fmaf(h1s[ko + kk], R[(size_t)(ko + kk) * FOURH + n], acc);
        part[warp][lane] = acc;
        __syncthreads();
        if (warp == 0) {
            float a = rb[n];
#pragma unroll
            for (int w = 0; w < 8; w++) a += part[w][lane];
            g_bias2[n] = a;
        }
    } else {
        int i = (bid - 64) * 256 + tid;           // < GG*HH
        int h = i & (HH - 1);
        g_c[i] = hsig(rb[h]) * tanhf(rb[2 * HH + h]);
    }
}

// ---------------- kconv_all: R -> R^T hi/lo ; MW -> hi/lo + transposed -----
__global__ __launch_bounds__(256) void kconv_all(const float* __restrict__ R,
                                                 const float* __restrict__ MW) {
    __shared__ float tile[32][33];
    int bid = blockIdx.x;
    int tx = threadIdx.x & 31, ty = threadIdx.x >> 5;  // 32 x 8
    if (bid < 2048) {
        int k0 = (bid & 31) * 32, n0 = (bid >> 5) * 32;
#pragma unroll
        for (int i = ty; i < 32; i += 8)
            tile[i][tx] = R[(size_t)(k0 + i) * FOURH + n0 + tx];
        __syncthreads();
#pragma unroll
        for (int i = ty; i < 32; i += 8) {
            float v = tile[tx][i];                 // = R[k0+tx][n0+i]
            __nv_bfloat16 hi = __float2bfloat16(v);
            size_t o = (size_t)(n0 + i) * TWOH + k0 + tx;
            g_bhi[o] = hi;
            g_blo[o] = __float2bfloat16(v - __bfloat162float(hi));
        }
    } else {
        int idx = bid - 2048;
        int h0 = (idx & 15) * 32, f0 = (idx >> 4) * 32;
#pragma unroll
        for (int i = ty; i < 32; i += 8) {
            float v = MW[(size_t)(f0 + i) * HH + h0 + tx];
            tile[i][tx] = v;
            __nv_bfloat16 hi = __float2bfloat16(v);
            size_t o = (size_t)(f0 + i) * HH + h0 + tx;
            g_mwhi[o] = hi;
            g_mwlo[o] = __float2bfloat16(v - __bfloat162float(hi));
        }
        __syncthreads();
#pragma unroll
        for (int i = ty; i < 32; i += 8) {
            float v = tile[tx][i];                 // = MW[f0+tx][h0+i]
            __nv_bfloat16 hi = __float2bfloat16(v);
            size_t o = (size_t)(h0 + i) * FF + f0 + tx;
            g_mthi[o] = hi;
            g_mtlo[o] = __float2bfloat16(v - __bfloat162float(hi));
        }
    }
}

// ---------------- K1: LSTM gates (+ emits bf16 hi/lo of h) -----------------
__global__ __launch_bounds__(256) void k1_gates(float* __restrict__ out) {
    int i  = blockIdx.x * 256 + threadIdx.x;
    int hh = i & (HH - 1);
    int g  = i >> 9;
    const float* zr = g_z + (size_t)g * FOURH;
    float zi = zr[hh], zf = zr[HH + hh], zc = zr[2 * HH + hh], zo = zr[3 * HH + hh];
    float c = hsig(zf) * g_c[i] + hsig(zi) * tanhf(zc);
    g_c[i] = c;
    float h = hsig(zo) * tanhf(c);
    size_t o = (size_t)g * TWOH + hh;
    out[o] = h;
    __nv_bfloat16 hi = __float2bfloat16(h);
    g_ahi[o] = hi;
    g_alo[o] = __float2bfloat16(h - __bfloat162float(hi));
}

// ---------------- K3: per-segment softmax + weighted feature sum -----------
// v4: cp.async staging; e-phase uses 4 threads/node (all 8 warps busy).
__global__ __launch_bounds__(256) void k3_seg(const float* __restrict__ feat,
                                              const float* __restrict__ wts,
                                              int use_w1) {
    int g = blockIdx.x;
    int tid = threadIdx.x;
    __shared__ __align__(16) float fs[NPS][FF + 4];
    __shared__ float ws[FF];
    __shared__ float as[NPS];
    __shared__ float es[NPS];
    __shared__ float red[16];
    __shared__ float red2[FF];

    // ---- stage features via cp.async: 2048 x 16B, 8 per thread
    const float* fp = feat + (size_t)g * NPS * FF;
    uint32_t sb;
    asm("{ .reg .u64 t; cvta.to.shared.u64 t, %1; cvt.u32.u64 %0, t; }"
        : "=r"(sb) : "l"((const void*)fs));
#pragma unroll
    for (int i = 0; i < 8; i++) {
        int idx = tid + (i << 8);             // 0..2047
        int node = idx >> 5;
        int col  = (idx & 31) << 2;
        uint32_t dst = sb + (uint32_t)(node * (FF + 4) + col) * 4;
        asm volatile("cp.async.cg.shared.global [%0], [%1], 16;"
                     :: "r"(dst), "l"(fp + (size_t)idx * 4) : "memory");
    }
    asm volatile("cp.async.commit_group;" ::: "memory");
    if (tid < FF) {
        const float* wp = use_w1 ? g_w1 : (g_w + (size_t)g * FF);
        ws[tid] = wp[tid];
    }
    asm volatile("cp.async.wait_group 0;" ::: "memory");
    __syncthreads();

    // ---- e_n = f_n . w : 4 threads per node, 32 cols each
    {
        int node = tid >> 2;
        int q    = (tid & 3) << 5;             // col base 0/32/64/96
        float acc = 0.f;
#pragma unroll
        for (int f = 0; f < 32; f += 4) {
            float4 fv = *(const float4*)&fs[node][q + f];
            float4 wv = *(const float4*)&ws[q + f];
            acc = fmaf(fv.x, wv.x, acc); acc = fmaf(fv.y, wv.y, acc);
            acc = fmaf(fv.z, wv.z, acc); acc = fmaf(fv.w, wv.w, acc);
        }
        acc += __shfl_xor_sync(0xffffffffu, acc, 1);
        acc += __shfl_xor_sync(0xffffffffu, acc, 2);
        if ((tid & 3) == 0) es[node] = acc;
    }
    __syncthreads();

    float e = (tid < NPS) ? es[tid] : -1e30f;
    float mx = e;
#pragma unroll
    for (int o = 16; o > 0; o >>= 1) mx = fmaxf(mx, __shfl_xor_sync(0xffffffffu, mx, o));
    if ((tid & 31) == 0) red[tid >> 5] = mx;
    __syncthreads();
    mx = fmaxf(fmaxf(red[0], red[1]), -1e30f);   // only warps 0,1 hold real e

    float ex = 0.f;
    if (tid < NPS) ex = __expf(e - mx) * wts[(size_t)g * NPS + tid];
    float sm = ex;
#pragma unroll
    for (int o = 16; o > 0; o >>= 1) sm += __shfl_xor_sync(0xffffffffu, sm, o);
    if ((tid & 31) == 0) red[8 + (tid >> 5)] = sm;
    __syncthreads();
    sm = red[8] + red[9];
    if (tid < NPS) as[tid] = ex / sm;
    __syncthreads();

    // ---- s_f = sum_n a_n f[n][f]  (256 threads: 2 halves of 32 nodes)
    int col  = tid & (FF - 1);
    int half = tid >> 7;
    int nb   = half << 5;
    float acc = 0.f;
#pragma unroll 16
    for (int n = 0; n < 32; n++) acc = fmaf(as[nb + n], fs[nb + n][col], acc);
    if (half) red2[col] = acc;
    __syncthreads();
    if (!half) {
        float v = acc + red2[col];
        size_t o = (size_t)g * FF + col;
        __nv_bfloat16 hi = __float2bfloat16(v);
        g_shi[o] = hi;
        g_slo[o] = __float2bfloat16(v - __bfloat162float(hi));
    }
}

// ---------------- KG: generic bf16 hi/lo split mma GEMM --------------------
// C[M,N] = A[M,K] @ B^T[N,K] (+bias) via 3 bf16 products.
// BM=32*MT, BN=128, BK=32 (2 k-halves per smem stage -> half the barriers),
// 8 warps, 2-stage cp.async pipeline (dyn smem 80KB), ldmatrix.x4.
#define LDSR 40                        // 32 + 8 pad (bf16); row = 80B
#define MATE (128 * LDSR)              // 5120 elements
#define STGE (4 * MATE)                // 20480 elements = 40960 B per stage
#define KG_DSM (2 * STGE * 2)          // 81920 bytes

template <int MT, int ASRC, int BSRC, int LDA, int LDB, int OUTSEL>
__global__ __launch_bounds__(256, 2) void kg_mma(
    int aoff, int boff, int K, float* __restrict__ outp,
    const float* __restrict__ bias, int use_b2)
{
    const __nv_bfloat16* __restrict__ Ahi = (ASRC == 0 ? g_ahi : g_shi) + aoff;
    const __nv_bfloat16* __restrict__ Alo = (ASRC == 0 ? g_alo : g_slo) + aoff;
    const __nv_bfloat16* __restrict__ Bhi =
        (BSRC == 0 ? g_bhi : BSRC == 1 ? g_mwhi : g_mthi) + boff;
    const __nv_bfloat16* __restrict__ Blo =
        (BSRC == 0 ? g_blo : BSRC == 1 ? g_mwlo : g_mtlo) + boff;

    extern __shared__ __align__(16) __nv_bfloat16 smem[];   // 2 stages
    int tid = threadIdx.x;
    int lane = tid & 31, wid = tid >> 5;
    int wm = wid >> 2, wn = wid & 3;          // 2 x 4 warp grid
    int nblk = blockIdx.x << 7;
    int mblk = blockIdx.y * (32 * MT);
    int g8 = lane >> 2;
    int t2 = (lane & 3) << 1;

    int sr = tid >> 1;
    int sc = (tid & 1) << 3;                  // 16B chunk base within 32 cols
    uint32_t sbase;
    asm("{ .reg .u64 t; cvta.to.shared.u64 t, %1; cvt.u32.u64 %0, t; }"
        : "=r"(sbase) : "l"((const void*)smem));
    uint32_t soff = (uint32_t)(sr * LDSR + sc) * 2;

    uint32_t a_lm = (uint32_t)(((wm * (MT * 16)) + (lane & 15)) * LDSR +
                               ((lane >> 4) << 3)) * 2;
    uint32_t b_lm = (uint32_t)(2 * MATE +
                               ((wn * 32) + (((lane >> 3) >> 1) << 3) + (lane & 7)) * LDSR +
                               (((lane >> 3) & 1) << 3)) * 2;

    float acc[MT][4][4];
#pragma unroll
    for (int a = 0; a < MT; a++)
#pragma unroll
        for (int b = 0; b < 4; b++)
#pragma unroll
            for (int c = 0; c < 4; c++) acc[a][b][c] = 0.f;

    int nch = K >> 5;                          // BK = 32

#define LOAD_STAGE(T, ST) do {                                                  \
    int kg_ = (T) << 5;                                                         \
    _Pragma("unroll")                                                           \
    for (int c_ = 0; c_ < 2; c_++) {                                            \
        uint32_t sb_ = sbase + (uint32_t)(ST) * (STGE * 2) + soff + c_ * 32;    \
        int col_ = kg_ + sc + c_ * 16;                                          \
        const __nv_bfloat16* b_ = Bhi + (size_t)(nblk + sr) * LDB + col_;       \
        if (sr < 32 * MT) {                                                     \
            const __nv_bfloat16* a_ = Ahi + (size_t)(mblk + sr) * LDA + col_;   \
            asm volatile("cp.async.cg.shared.global [%0], [%1], 16;"            \
                         :: "r"(sb_), "l"(a_) : "memory");                      \
            asm volatile("cp.async.cg.shared.global [%0], [%1], 16;"            \
                         :: "r"(sb_ + MATE * 2), "l"(Alo + (a_ - Ahi)) : "memory"); \
        }                                                                       \
        asm volatile("cp.async.cg.shared.global [%0], [%1], 16;"                \
                     :: "r"(sb_ + 2 * MATE * 2), "l"(b_) : "memory");           \
        asm volatile("cp.async.cg.shared.global [%0], [%1], 16;"                \
                     :: "r"(sb_ + 3 * MATE * 2), "l"(Blo + (b_ - Bhi)) : "memory"); \
    }                                                                           \
    asm volatile("cp.async.commit_group;" ::: "memory");                       \
} while (0)

#define LDSM_X4(r0, r1, r2, r3, addr)                                           \
    asm volatile("ldmatrix.sync.aligned.m8n8.x4.shared.b16 {%0,%1,%2,%3}, [%4];"\
        : "=r"(r0), "=r"(r1), "=r"(r2), "=r"(r3) : "r"(addr) : "memory")

    LOAD_STAGE(0, 0);
    asm volatile("cp.async.wait_group 0;" ::: "memory");
    __syncthreads();

    for (int t = 0; t < nch; t++) {
        if (t + 1 < nch) LOAD_STAGE(t + 1, (t + 1) & 1);

        uint32_t sb = sbase + (uint32_t)(t & 1) * (STGE * 2);
#pragma unroll
        for (int ks = 0; ks < 2; ks++) {
            uint32_t koff = (uint32_t)ks * 32;            // 16 cols = 32 bytes
            uint32_t bh[4][2], bl[4][2];
#pragma unroll
            for (int p = 0; p < 2; p++) {
                uint32_t ba = sb + b_lm + (uint32_t)(p * 16 * LDSR) * 2 + koff;
                LDSM_X4(bh[2 * p][0], bh[2 * p][1],
                        bh[2 * p + 1][0], bh[2 * p + 1][1], ba);
                LDSM_X4(bl[2 * p][0], bl[2 * p][1],
                        bl[2 * p + 1][0], bl[2 * p + 1][1],
                        ba + (uint32_t)(MATE * 2));
            }
#pragma unroll
            for (int mt = 0; mt < MT; mt++) {
                uint32_t aa = sb + a_lm + (uint32_t)(mt * 16 * LDSR) * 2 + koff;
                uint32_t ahf[4], alf[4];
                LDSM_X4(ahf[0], ahf[1], ahf[2], ahf[3], aa);
                LDSM_X4(alf[0], alf[1], alf[2], alf[3], aa + (uint32_t)(MATE * 2));
#pragma unroll
                for (int nt = 0; nt < 4; nt++) {
                    mma16816(acc[mt][nt], ahf, bh[nt]);
                    mma16816(acc[mt][nt], ahf, bl[nt]);
                    mma16816(acc[mt][nt], alf, bh[nt]);
                }
            }
        }

        if (t + 1 < nch) {
            asm volatile("cp.async.wait_group 0;" ::: "memory");
            __syncthreads();
        }
    }
#undef LOAD_STAGE
#undef LDSM_X4

    // ---- epilogue
    const float* bp = (OUTSEL == 0) ? (use_b2 ? g_bias2 : bias) : bias;
#pragma unroll
    for (int mt = 0; mt < MT; mt++) {
#pragma unroll
        for (int nt = 0; nt < 4; nt++) {
            int m = mblk + wm * (MT * 16) + mt * 16 + g8;
            int n = nblk + wn * 32 + nt * 8 + t2;
            float b0 = (OUTSEL == 1) ? 0.f : bp[n];
            float b1 = (OUTSEL == 1) ? 0.f : bp[n + 1];
            float2 v0 = make_float2(acc[mt][nt][0] + b0, acc[mt][nt][1] + b1);
            float2 v1 = make_float2(acc[mt][nt][2] + b0, acc[mt][nt][3] + b1);
            if (OUTSEL == 0) {
                *(float2*)(g_z + (size_t)m * FOURH + n) = v0;
                *(float2*)(g_z + (size_t)(m + 8) * FOURH + n) = v1;
            } else if (OUTSEL == 1) {
                *(float2*)(g_w + (size_t)m * FF + n) = v0;
                *(float2*)(g_w + (size_t)(m + 8) * FF + n) = v1;
            } else {
                size_t o0 = (size_t)m * TWOH + HH + n;
                size_t o1 = (size_t)(m + 8) * TWOH + HH + n;
                *(float2*)(outp + o0) = v0;
                *(float2*)(outp + o1) = v1;
                __nv_bfloat16 h0 = __float2bfloat16(v0.x);
                __nv_bfloat16 h1 = __float2bfloat16(v0.y);
                __nv_bfloat16 h2 = __float2bfloat16(v1.x);
                __nv_bfloat16 h3 = __float2bfloat16(v1.y);
                *(__nv_bfloat162*)(g_ahi + o0) = __nv_bfloat162{h0, h1};
                *(__nv_bfloat162*)(g_ahi + o1) = __nv_bfloat162{h2, h3};
                *(__nv_bfloat162*)(g_alo + o0) = __nv_bfloat162{
                    __float2bfloat16(v0.x - __bfloat162float(h0)),
                    __float2bfloat16(v0.y - __bfloat162float(h1))};
                *(__nv_bfloat162*)(g_alo + o1) = __nv_bfloat162{
                    __float2bfloat16(v1.x - __bfloat162float(h2)),
                    __float2bfloat16(v1.y - __bfloat162float(h3))};
            }
        }
    }
}

// ---------------- launch ----------------------------------------------------
extern "C" void kernel_launch(void* const* d_in, const int* in_sizes, int n_in,
                              void* d_out, int out_size) {
    const float* feat = (const float*)d_in[0];   // features (1, N, F)
    const float* wts  = (const float*)d_in[1];   // weights  (1, N)
    const float* MW   = (const float*)d_in[3];   // m_weight (F, H)
    const float* mb   = (const float*)d_in[4];   // m_bias   (H,)
    const float* R    = (const float*)d_in[5];   // recurrent_kernel (2H, 4H)
    const float* rb   = (const float*)d_in[6];   // recurrent_bias   (4H,)
    float* out = (float*)d_out;                  // q_star (1, G, 2H)

    cudaFuncSetAttribute(kg_mma<4, 0, 0, TWOH, TWOH, 0>,
                         cudaFuncAttributeMaxDynamicSharedMemorySize, KG_DSM);
    cudaFuncSetAttribute(kg_mma<1, 0, 1, TWOH, HH, 1>,
                         cudaFuncAttributeMaxDynamicSharedMemorySize, KG_DSM);
    cudaFuncSetAttribute(kg_mma<2, 1, 2, FF, FF, 2>,
                         cudaFuncAttributeMaxDynamicSharedMemorySize, KG_DSM);

    // ---- prologue (launch #4 = kg_mma k4 so the profiler samples the GEMM)
    k0_w1v2  <<<16, 256>>>(rb, MW);
    kconv_all<<<2112, 256>>>(R, MW);
    k3_seg   <<<GG, 256>>>(feat, wts, 1);
    kg_mma<2, 1, 2, FF, FF, 2><<<dim3(HH / 128, GG / 64), 256, KG_DSM>>>(
        0, 0, FF, out, mb, 0);                              // k4: r1
    k0_cb    <<<64 + (GG * HH) / 256, 256>>>(R, rb);

    // ---- iteration 2 (h1 folded into bias2 -> half-K GEMM over r only)
    kg_mma<4, 0, 0, TWOH, TWOH, 0><<<dim3(FOURH / 128, GG / 128), 256, KG_DSM>>>(
        HH, HH, HH, out, rb, 1);                            // k5
    k1_gates<<<(GG * HH) / 256, 256>>>(out);
    kg_mma<1, 0, 1, TWOH, HH, 1><<<dim3(FF / 128, GG / 32), 256, KG_DSM>>>(
        0, 0, HH, out, rb, 0);                              // k2: w  (BM=32)
    k3_seg  <<<GG, 256>>>(feat, wts, 0);
    kg_mma<2, 1, 2, FF, FF, 2><<<dim3(HH / 128, GG / 64), 256, KG_DSM>>>(
        0, 0, FF, out, mb, 0);                              // k4: r2

    // ---- iteration 3 (full K = 2H)
    kg_mma<4, 0, 0, TWOH, TWOH, 0><<<dim3(FOURH / 128, GG / 128), 256, KG_DSM>>>(
        0, 0, TWOH, out, rb, 0);                            // k5
    k1_gates<<<(GG * HH) / 256, 256>>>(out);
    kg_mma<1, 0, 1, TWOH, HH, 1><<<dim3(FF / 128, GG / 32), 256, KG_DSM>>>(
        0, 0, HH, out, rb, 0);                              // k2: w  (BM=32)
    k3_seg  <<<GG, 256>>>(feat, wts, 0);
    kg_mma<2, 1, 2, FF, FF, 2><<<dim3(HH / 128, GG / 64), 256, KG_DSM>>>(
        0, 0, FF, out, mb, 0);                              // k4: r3
}

// round 16
// speedup vs baseline: 1.0128x; 1.0128x over previous
#include <cuda_runtime.h>
#include <cuda_bf16.h>
#include <math.h>
#include <stdint.h>

#define GG    4096
#define HH    512
#define FF    128
#define NPS   64
#define TWOH  1024
#define FOURH 2048

// ---------------- scratch (device globals; no allocation allowed) ----------
// NOTE: device-global symbols must only be referenced from DEVICE code.
__device__ float g_z[GG * FOURH];     // z = q_star @ R + bias
__device__ float g_c[GG * HH];        // LSTM cell state
__device__ float g_w[GG * FF];        // w_g = h_g @ MW^T
__device__ float g_w1[FF];
__device__ float g_bias2[FOURH];      // rb + h1 @ R_top
__device__ __nv_bfloat16 g_ahi[GG * TWOH];      // q_star hi (bf16)
__device__ __nv_bfloat16 g_alo[GG * TWOH];      // q_star lo (bf16)
__device__ __nv_bfloat16 g_bhi[FOURH * TWOH];   // R^T hi   [n][k]
__device__ __nv_bfloat16 g_blo[FOURH * TWOH];   // R^T lo   [n][k]
__device__ __nv_bfloat16 g_shi[GG * FF];        // s hi
__device__ __nv_bfloat16 g_slo[GG * FF];        // s lo
__device__ __nv_bfloat16 g_mwhi[FF * HH];       // MW hi    [f][k]
__device__ __nv_bfloat16 g_mwlo[FF * HH];
__device__ __nv_bfloat16 g_mthi[HH * FF];       // MW^T hi  [h][f]
__device__ __nv_bfloat16 g_mtlo[HH * FF];

__device__ __forceinline__ float hsig(float x) {
    return __saturatef(fmaf(0.2f, x, 0.5f));
}
__device__ __forceinline__ void mma16816(float* c, const uint32_t* a,
                                         const uint32_t* b) {
    asm volatile(
        "mma.sync.aligned.m16n8k16.row.col.f32.bf16.bf16.f32 "
        "{%0,%1,%2,%3}, {%4,%5,%6,%7}, {%8,%9}, {%0,%1,%2,%3};"
        : "+f"(c[0]), "+f"(c[1]), "+f"(c[2]), "+f"(c[3])
        : "r"(a[0]), "r"(a[1]), "r"(a[2]), "r"(a[3]), "r"(b[0]), "r"(b[1]));
}

// ---------------- k0_w1v2: w1[f] = sum_k MW[f,k]*h1[k], h1 inline ---------
__global__ __launch_bounds__(256) void k0_w1v2(const float* __restrict__ rb,
                                               const float* __restrict__ MW) {
    int warp = blockIdx.x * 8 + (threadIdx.x >> 5);   // 0..127
    int lane = threadIdx.x & 31;
    const float* row = MW + (size_t)warp * HH;
    float acc = 0.f;
#pragma unroll 4
    for (int k = lane; k < HH; k += 32) {
        float c  = hsig(rb[k]) * tanhf(rb[2 * HH + k]);
        float h1 = hsig(rb[3 * HH + k]) * tanhf(c);
        acc = fmaf(row[k], h1, acc);
    }
#pragma unroll
    for (int o = 16; o > 0; o >>= 1) acc += __shfl_xor_sync(0xffffffffu, acc, o);
    if (lane == 0) g_w1[warp] = acc;
}

// ---------------- k0_cb: fused c-init broadcast + bias2 single pass --------
__global__ __launch_bounds__(256) void k0_cb(const float* __restrict__ R,
                                             const float* __restrict__ rb) {
    int bid = blockIdx.x;
    int tid = threadIdx.x;
    if (bid < 64) {
        __shared__ float h1s[HH];
        __shared__ float part[8][32];
        int lane = tid & 31, warp = tid >> 5;
        for (int k = tid; k < HH; k += 256) {
            float c = hsig(rb[k]) * tanhf(rb[2 * HH + k]);
            h1s[k] = hsig(rb[3 * HH + k]) * tanhf(c);
        }
        __syncthreads();
        int n  = bid * 32 + lane;
        int ko = warp * 64;
        float acc = 0.f;
#pragma unroll 8
        for (int kk = 0; kk < 64; kk++)
            acc = fmaf(h1s[ko + kk], R[(size_t)(ko + kk) * FOURH + n], acc);
        part[warp][lane] = acc;
        __syncthreads();
        if (warp == 0) {
            float a = rb[n];
#pragma unroll
            for (int w = 0; w < 8; w++) a += part[w][lane];
            g_bias2[n] = a;
        }
    } else {
        int i = (bid - 64) * 256 + tid;           // < GG*HH
        int h = i & (HH - 1);
        g_c[i] = hsig(rb[h]) * tanhf(rb[2 * HH + h]);
    }
}

// ---------------- kconv_all: R -> R^T hi/lo ; MW -> hi/lo + transposed -----
__global__ __launch_bounds__(256) void kconv_all(const float* __restrict__ R,
                                                 const float* __restrict__ MW) {
    __shared__ float tile[32][33];
    int bid = blockIdx.x;
    int tx = threadIdx.x & 31, ty = threadIdx.x >> 5;  // 32 x 8
    if (bid < 2048) {
        int k0 = (bid & 31) * 32, n0 = (bid >> 5) * 32;
#pragma unroll
        for (int i = ty; i < 32; i += 8)
            tile[i][tx] = R[(size_t)(k0 + i) * FOURH + n0 + tx];
        __syncthreads();
#pragma unroll
        for (int i = ty; i < 32; i += 8) {
            float v = tile[tx][i];                 // = R[k0+tx][n0+i]
            __nv_bfloat16 hi = __float2bfloat16(v);
            size_t o = (size_t)(n0 + i) * TWOH + k0 + tx;
            g_bhi[o] = hi;
            g_blo[o] = __float2bfloat16(v - __bfloat162float(hi));
        }
    } else {
        int idx = bid - 2048;
        int h0 = (idx & 15) * 32, f0 = (idx >> 4) * 32;
#pragma unroll
        for (int i = ty; i < 32; i += 8) {
            float v = MW[(size_t)(f0 + i) * HH + h0 + tx];
            tile[i][tx] = v;
            __nv_bfloat16 hi = __float2bfloat16(v);
            size_t o = (size_t)(f0 + i) * HH + h0 + tx;
            g_mwhi[o] = hi;
            g_mwlo[o] = __float2bfloat16(v - __bfloat162float(hi));
        }
        __syncthreads();
#pragma unroll
        for (int i = ty; i < 32; i += 8) {
            float v = tile[tx][i];                 // = MW[f0+tx][h0+i]
            __nv_bfloat16 hi = __float2bfloat16(v);
            size_t o = (size_t)(h0 + i) * FF + f0 + tx;
            g_mthi[o] = hi;
            g_mtlo[o] = __float2bfloat16(v - __bfloat162float(hi));
        }
    }
}

// ---------------- K1: LSTM gates (+ emits bf16 hi/lo of h) -----------------
__global__ __launch_bounds__(256) void k1_gates(float* __restrict__ out) {
    int i  = blockIdx.x * 256 + threadIdx.x;
    int hh = i & (HH - 1);
    int g  = i >> 9;
    const float* zr = g_z + (size_t)g * FOURH;
    float zi = zr[hh], zf = zr[HH + hh], zc = zr[2 * HH + hh], zo = zr[3 * HH + hh];
    float c = hsig(zf) * g_c[i] + hsig(zi) * tanhf(zc);
    g_c[i] = c;
    float h = hsig(zo) * tanhf(c);
    size_t o = (size_t)g * TWOH + hh;
    out[o] = h;
    __nv_bfloat16 hi = __float2bfloat16(h);
    g_ahi[o] = hi;
    g_alo[o] = __float2bfloat16(h - __bfloat162float(hi));
}

// ---------------- K3: per-segment softmax + weighted feature sum -----------
// v4: cp.async staging; e-phase uses 4 threads/node (all 8 warps busy).
__global__ __launch_bounds__(256) void k3_seg(const float* __restrict__ feat,
                                              const float* __restrict__ wts,
                                              int use_w1) {
    int g = blockIdx.x;
    int tid = threadIdx.x;
    __shared__ __align__(16) float fs[NPS][FF + 4];
    __shared__ float ws[FF];
    __shared__ float as[NPS];
    __shared__ float es[NPS];
    __shared__ float red[16];
    __shared__ float red2[FF];

    const float* fp = feat + (size_t)g * NPS * FF;
    uint32_t sb;
    asm("{ .reg .u64 t; cvta.to.shared.u64 t, %1; cvt.u32.u64 %0, t; }"
        : "=r"(sb) : "l"((const void*)fs));
#pragma unroll
    for (int i = 0; i < 8; i++) {
        int idx = tid + (i << 8);             // 0..2047
        int node = idx >> 5;
        int col  = (idx & 31) << 2;
        uint32_t dst = sb + (uint32_t)(node * (FF + 4) + col) * 4;
        asm volatile("cp.async.cg.shared.global [%0], [%1], 16;"
                     :: "r"(dst), "l"(fp + (size_t)idx * 4) : "memory");
    }
    asm volatile("cp.async.commit_group;" ::: "memory");
    if (tid < FF) {
        const float* wp = use_w1 ? g_w1 : (g_w + (size_t)g * FF);
        ws[tid] = wp[tid];
    }
    asm volatile("cp.async.wait_group 0;" ::: "memory");
    __syncthreads();

    // ---- e_n = f_n . w : 4 threads per node, 32 cols each
    {
        int node = tid >> 2;
        int q    = (tid & 3) << 5;             // col base 0/32/64/96
        float acc = 0.f;
#pragma unroll
        for (int f = 0; f < 32; f += 4) {
            float4 fv = *(const float4*)&fs[node][q + f];
            float4 wv = *(const float4*)&ws[q + f];
            acc = fmaf(fv.x, wv.x, acc); acc = fmaf(fv.y, wv.y, acc);
            acc = fmaf(fv.z, wv.z, acc); acc = fmaf(fv.w, wv.w, acc);
        }
        acc += __shfl_xor_sync(0xffffffffu, acc, 1);
        acc += __shfl_xor_sync(0xffffffffu, acc, 2);
        if ((tid & 3) == 0) es[node] = acc;
    }
    __syncthreads();

    float e = (tid < NPS) ? es[tid] : -1e30f;
    float mx = e;
#pragma unroll
    for (int o = 16; o > 0; o >>= 1) mx = fmaxf(mx, __shfl_xor_sync(0xffffffffu, mx, o));
    if ((tid & 31) == 0) red[tid >> 5] = mx;
    __syncthreads();
    mx = fmaxf(fmaxf(red[0], red[1]), -1e30f);

    float ex = 0.f;
    if (tid < NPS) ex = __expf(e - mx) * wts[(size_t)g * NPS + tid];
    float sm = ex;
#pragma unroll
    for (int o = 16; o > 0; o >>= 1) sm += __shfl_xor_sync(0xffffffffu, sm, o);
    if ((tid & 31) == 0) red[8 + (tid >> 5)] = sm;
    __syncthreads();
    sm = red[8] + red[9];
    if (tid < NPS) as[tid] = ex / sm;
    __syncthreads();

    int col  = tid & (FF - 1);
    int half = tid >> 7;
    int nb   = half << 5;
    float acc = 0.f;
#pragma unroll 16
    for (int n = 0; n < 32; n++) acc = fmaf(as[nb + n], fs[nb + n][col], acc);
    if (half) red2[col] = acc;
    __syncthreads();
    if (!half) {
        float v = acc + red2[col];
        size_t o = (size_t)g * FF + col;
        __nv_bfloat16 hi = __float2bfloat16(v);
        g_shi[o] = hi;
        g_slo[o] = __float2bfloat16(v - __bfloat162float(hi));
    }
}

// ---------------- KG: generic bf16 hi/lo split mma GEMM --------------------
// C[M,N] = A[M,K] @ B^T[N,K] (+bias) via 3 bf16 products.
// BM=32*MT, BN=128, BK=16, 8 warps, 3-stage cp.async pipeline (dyn smem),
// ldmatrix.x4 fragment loads. (round-13 hot loop: no spills, at mma ceiling)
#define LDSR 24                        // 16 + 8 pad (bf16); row = 48B
#define MATE (128 * LDSR)
#define STGE (4 * MATE)
#define KG_DSM (3 * STGE * 2)          // 73728 bytes

template <int MT, int ASRC, int BSRC, int LDA, int LDB, int OUTSEL>
__global__ __launch_bounds__(256, 2) void kg_mma(
    int aoff, int boff, int K, float* __restrict__ outp,
    const float* __restrict__ bias, int use_b2)
{
    const __nv_bfloat16* __restrict__ Ahi = (ASRC == 0 ? g_ahi : g_shi) + aoff;
    const __nv_bfloat16* __restrict__ Alo = (ASRC == 0 ? g_alo : g_slo) + aoff;
    const __nv_bfloat16* __restrict__ Bhi =
        (BSRC == 0 ? g_bhi : BSRC == 1 ? g_mwhi : g_mthi) + boff;
    const __nv_bfloat16* __restrict__ Blo =
        (BSRC == 0 ? g_blo : BSRC == 1 ? g_mwlo : g_mtlo) + boff;

    extern __shared__ __align__(16) __nv_bfloat16 smem[];   // 3 stages
    int tid = threadIdx.x;
    int lane = tid & 31, wid = tid >> 5;
    int wm = wid >> 2, wn = wid & 3;          // 2 x 4 warp grid
    int nblk = blockIdx.x << 7;
    int mblk = blockIdx.y * (32 * MT);
    int g8 = lane >> 2;
    int t2 = (lane & 3) << 1;

    int sr = tid >> 1;
    int sc = (tid & 1) << 3;
    uint32_t sbase;
    asm("{ .reg .u64 t; cvta.to.shared.u64 t, %1; cvt.u32.u64 %0, t; }"
        : "=r"(sbase) : "l"((const void*)smem));
    uint32_t soff = (uint32_t)(sr * LDSR + sc) * 2;

    uint32_t a_lm = (uint32_t)(((wm * (MT * 16)) + (lane & 15)) * LDSR +
                               ((lane >> 4) << 3)) * 2;
    uint32_t b_lm = (uint32_t)(2 * MATE +
                               ((wn * 32) + (((lane >> 3) >> 1) << 3) + (lane & 7)) * LDSR +
                               (((lane >> 3) & 1) << 3)) * 2;

    float acc[MT][4][4];
#pragma unroll
    for (int a = 0; a < MT; a++)
#pragma unroll
        for (int b = 0; b < 4; b++)
#pragma unroll
            for (int c = 0; c < 4; c++) acc[a][b][c] = 0.f;

    int nch = K >> 4;

#define LOAD_STAGE(T, ST) do {                                                  \
    int kg_ = (T) << 4;                                                         \
    uint32_t sb_ = sbase + (uint32_t)(ST) * (STGE * 2) + soff;                  \
    const __nv_bfloat16* b_ = Bhi + (size_t)(nblk + sr) * LDB + kg_ + sc;       \
    if (sr < 32 * MT) {                                                         \
        const __nv_bfloat16* a_ = Ahi + (size_t)(mblk + sr) * LDA + kg_ + sc;   \
        asm volatile("cp.async.cg.shared.global [%0], [%1], 16;"                \
                     :: "r"(sb_), "l"(a_) : "memory");                          \
        asm volatile("cp.async.cg.shared.global [%0], [%1], 16;"                \
                     :: "r"(sb_ + MATE * 2), "l"(Alo + (a_ - Ahi)) : "memory"); \
    }                                                                           \
    asm volatile("cp.async.cg.shared.global [%0], [%1], 16;"                    \
                 :: "r"(sb_ + 2 * MATE * 2), "l"(b_) : "memory");               \
    asm volatile("cp.async.cg.shared.global [%0], [%1], 16;"                    \
                 :: "r"(sb_ + 3 * MATE * 2), "l"(Blo + (b_ - Bhi)) : "memory"); \
    asm volatile("cp.async.commit_group;" ::: "memory");                       \
} while (0)

#define LDSM_X4(r0, r1, r2, r3, addr)                                           \
    asm volatile("ldmatrix.sync.aligned.m8n8.x4.shared.b16 {%0,%1,%2,%3}, [%4];"\
        : "=r"(r0), "=r"(r1), "=r"(r2), "=r"(r3) : "r"(addr) : "memory")

    // prologue: fill 2 stages (all GEMMs here have nch >= 8)
    LOAD_STAGE(0, 0);
    LOAD_STAGE(1, 1);
    asm volatile("cp.async.wait_group 1;" ::: "memory");
    __syncthreads();

    int st = 0;                                // stage of chunk t
    for (int t = 0; t < nch; t++) {
        if (t + 2 < nch) {
            int st2 = st + 2;
            if (st2 >= 3) st2 -= 3;
            LOAD_STAGE(t + 2, st2);
        }

        uint32_t sb = sbase + (uint32_t)st * (STGE * 2);
        uint32_t bh[4][2], bl[4][2];
#pragma unroll
        for (int p = 0; p < 2; p++) {
            uint32_t ba = sb + b_lm + (uint32_t)(p * 16 * LDSR) * 2;
            LDSM_X4(bh[2 * p][0], bh[2 * p][1], bh[2 * p + 1][0], bh[2 * p + 1][1], ba);
            LDSM_X4(bl[2 * p][0], bl[2 * p][1], bl[2 * p + 1][0], bl[2 * p + 1][1],
                    ba + (uint32_t)(MATE * 2));
        }
#pragma unroll
        for (int mt = 0; mt < MT; mt++) {
            uint32_t aa = sb + a_lm + (uint32_t)(mt * 16 * LDSR) * 2;
            uint32_t ahf[4], alf[4];
            LDSM_X4(ahf[0], ahf[1], ahf[2], ahf[3], aa);
            LDSM_X4(alf[0], alf[1], alf[2], alf[3], aa + (uint32_t)(MATE * 2));
#pragma unroll
            for (int nt = 0; nt < 4; nt++) {
                mma16816(acc[mt][nt], ahf, bh[nt]);
                mma16816(acc[mt][nt], ahf, bl[nt]);
                mma16816(acc[mt][nt], alf, bh[nt]);
            }
        }

        if (t + 1 < nch) {
            if (t + 2 < nch) {
                asm volatile("cp.async.wait_group 1;" ::: "memory");
            } else {
                asm volatile("cp.async.wait_group 0;" ::: "memory");
            }
            __syncthreads();
        }
        if (++st == 3) st = 0;
    }
#undef LOAD_STAGE
#undef LDSM_X4

    // ---- epilogue
    const float* bp = (OUTSEL == 0) ? (use_b2 ? g_bias2 : bias) : bias;
#pragma unroll
    for (int mt = 0; mt < MT; mt++) {
#pragma unroll
        for (int nt = 0; nt < 4; nt++) {
            int m = mblk + wm * (MT * 16) + mt * 16 + g8;
            int n = nblk + wn * 32 + nt * 8 + t2;
            float b0 = (OUTSEL == 1) ? 0.f : bp[n];
            float b1 = (OUTSEL == 1) ? 0.f : bp[n + 1];
            float2 v0 = make_float2(acc[mt][nt][0] + b0, acc[mt][nt][1] + b1);
            float2 v1 = make_float2(acc[mt][nt][2] + b0, acc[mt][nt][3] + b1);
            if (OUTSEL == 0) {
                *(float2*)(g_z + (size_t)m * FOURH + n) = v0;
                *(float2*)(g_z + (size_t)(m + 8) * FOURH + n) = v1;
            } else if (OUTSEL == 1) {
                *(float2*)(g_w + (size_t)m * FF + n) = v0;
                *(float2*)(g_w + (size_t)(m + 8) * FF + n) = v1;
            } else {
                size_t o0 = (size_t)m * TWOH + HH + n;
                size_t o1 = (size_t)(m + 8) * TWOH + HH + n;
                *(float2*)(outp + o0) = v0;
                *(float2*)(outp + o1) = v1;
                __nv_bfloat16 h0 = __float2bfloat16(v0.x);
                __nv_bfloat16 h1 = __float2bfloat16(v0.y);
                __nv_bfloat16 h2 = __float2bfloat16(v1.x);
                __nv_bfloat16 h3 = __float2bfloat16(v1.y);
                *(__nv_bfloat162*)(g_ahi + o0) = __nv_bfloat162{h0, h1};
                *(__nv_bfloat162*)(g_ahi + o1) = __nv_bfloat162{h2, h3};
                *(__nv_bfloat162*)(g_alo + o0) = __nv_bfloat162{
                    __float2bfloat16(v0.x - __bfloat162float(h0)),
                    __float2bfloat16(v0.y - __bfloat162float(h1))};
                *(__nv_bfloat162*)(g_alo + o1) = __nv_bfloat162{
                    __float2bfloat16(v1.x - __bfloat162float(h2)),
                    __float2bfloat16(v1.y - __bfloat162float(h3))};
            }
        }
    }
}

// ---------------- launch ----------------------------------------------------
extern "C" void kernel_launch(void* const* d_in, const int* in_sizes, int n_in,
                              void* d_out, int out_size) {
    const float* feat = (const float*)d_in[0];   // features (1, N, F)
    const float* wts  = (const float*)d_in[1];   // weights  (1, N)
    const float* MW   = (const float*)d_in[3];   // m_weight (F, H)
    const float* mb   = (const float*)d_in[4];   // m_bias   (H,)
    const float* R    = (const float*)d_in[5];   // recurrent_kernel (2H, 4H)
    const float* rb   = (const float*)d_in[6];   // recurrent_bias   (4H,)
    float* out = (float*)d_out;                  // q_star (1, G, 2H)

    cudaFuncSetAttribute(kg_mma<4, 0, 0, TWOH, TWOH, 0>,
                         cudaFuncAttributeMaxDynamicSharedMemorySize, KG_DSM);
    cudaFuncSetAttribute(kg_mma<1, 0, 1, TWOH, HH, 1>,
                         cudaFuncAttributeMaxDynamicSharedMemorySize, KG_DSM);
    cudaFuncSetAttribute(kg_mma<2, 1, 2, FF, FF, 2>,
                         cudaFuncAttributeMaxDynamicSharedMemorySize, KG_DSM);

    // ---- prologue (launch #4 = kg_mma k4 so the profiler samples the GEMM)
    k0_w1v2  <<<16, 256>>>(rb, MW);
    kconv_all<<<2112, 256>>>(R, MW);
    k3_seg   <<<GG, 256>>>(feat, wts, 1);
    kg_mma<2, 1, 2, FF, FF, 2><<<dim3(HH / 128, GG / 64), 256, KG_DSM>>>(
        0, 0, FF, out, mb, 0);                              // k4: r1
    k0_cb    <<<64 + (GG * HH) / 256, 256>>>(R, rb);

    // ---- iteration 2 (h1 folded into bias2 -> half-K GEMM over r only)
    kg_mma<4, 0, 0, TWOH, TWOH, 0><<<dim3(FOURH / 128, GG / 128), 256, KG_DSM>>>(
        HH, HH, HH, out, rb, 1);                            // k5
    k1_gates<<<(GG * HH) / 256, 256>>>(out);
    kg_mma<1, 0, 1, TWOH, HH, 1><<<dim3(FF / 128, GG / 32), 256, KG_DSM>>>(
        0, 0, HH, out, rb, 0);                              // k2: w  (BM=32)
    k3_seg  <<<GG, 256>>>(feat, wts, 0);
    kg_mma<2, 1, 2, FF, FF, 2><<<dim3(HH / 128, GG / 64), 256, KG_DSM>>>(
        0, 0, FF, out, mb, 0);                              // k4: r2

    // ---- iteration 3 (full K = 2H)
    kg_mma<4, 0, 0, TWOH, TWOH, 0><<<dim3(FOURH / 128, GG / 128), 256, KG_DSM>>>(
        0, 0, TWOH, out, rb, 0);                            // k5
    k1_gates<<<(GG * HH) / 256, 256>>>(out);
    kg_mma<1, 0, 1, TWOH, HH, 1><<<dim3(FF / 128, GG / 32), 256, KG_DSM>>>(
        0, 0, HH, out, rb, 0);                              // k2: w  (BM=32)
    k3_seg  <<<GG, 256>>>(feat, wts, 0);
    kg_mma<2, 1, 2, FF, FF, 2><<<dim3(HH / 128, GG / 64), 256, KG_DSM>>>(
        0, 0, FF, out, mb, 0);                              // k4: r3
}

// round 17
// speedup vs baseline: 1.5131x; 1.4940x over previous
#include <cuda_runtime.h>
#include <cuda_bf16.h>
#include <math.h>
#include <stdint.h>

#define GG    4096
#define HH    512
#define FF    128
#define NPS   64
#define TWOH  1024
#define FOURH 2048

// ---------------- scratch (device globals; no allocation allowed) ----------
// NOTE: device-global symbols must only be referenced from DEVICE code.
__device__ float g_z[GG * FOURH];     // z = q_star @ R' + bias
__device__ float g_c[GG * HH];        // LSTM cell state
__device__ float g_w[GG * FF];        // w_g = h_g @ MW^T
__device__ float g_h1[HH];
__device__ float g_c1[HH];
__device__ float g_w1[FF];
__device__ float g_bias2[FOURH];      // rb + h1 @ R_top + mb @ R_bot
__device__ float g_bias3[FOURH];      // rb + mb @ R_bot
__device__ float g_b2p[8 * FOURH];    // split-K partials (h1 @ R_top)
__device__ float g_b3p[8 * FOURH];    // split-K partials (mb @ R_bot)
__device__ __nv_bfloat16 g_ahi[GG * TWOH];      // A rows: [h(512) | s(128) | -]
__device__ __nv_bfloat16 g_alo[GG * TWOH];
__device__ __nv_bfloat16 g_bhi[FOURH * TWOH];   // B rows: [R_top^T(512)|C^T(128)|-]
__device__ __nv_bfloat16 g_blo[FOURH * TWOH];
__device__ __nv_bfloat16 g_chi[FOURH * FF];     // C^T = (MW @ R_bot)^T  [n][f]
__device__ __nv_bfloat16 g_clo[FOURH * FF];
__device__ __nv_bfloat16 g_mwhi[FF * HH];       // MW hi    [f][k]
__device__ __nv_bfloat16 g_mwlo[FF * HH];
__device__ __nv_bfloat16 g_mthi[HH * FF];       // MW^T hi  [h][f]
__device__ __nv_bfloat16 g_mtlo[HH * FF];

__device__ __forceinline__ float hsig(float x) {
    return __saturatef(fmaf(0.2f, x, 0.5f));
}
__device__ __forceinline__ void mma16816(float* c, const uint32_t* a,
                                         const uint32_t* b) {
    asm volatile(
        "mma.sync.aligned.m16n8k16.row.col.f32.bf16.bf16.f32 "
        "{%0,%1,%2,%3}, {%4,%5,%6,%7}, {%8,%9}, {%0,%1,%2,%3};"
        : "+f"(c[0]), "+f"(c[1]), "+f"(c[2]), "+f"(c[3])
        : "r"(a[0]), "r"(a[1]), "r"(a[2]), "r"(a[3]), "r"(b[0]), "r"(b[1]));
}

// ---------------- K0: iteration-1 analytic prologue ------------------------
__global__ void k0_init(const float* __restrict__ rb) {
    int h = threadIdx.x;                      // 512 threads
    float zi = rb[h], zc = rb[2 * HH + h], zo = rb[3 * HH + h];
    float c  = hsig(zi) * tanhf(zc);
    g_c1[h] = c;
    g_h1[h] = hsig(zo) * tanhf(c);
}
__global__ __launch_bounds__(256) void k0_bcast() {
    int i = blockIdx.x * 256 + threadIdx.x;
    g_c[i] = g_c1[i & (HH - 1)];
}
// w1[f] = sum_k MW[f,k] * h1[k] — one warp per f
__global__ __launch_bounds__(256) void k0_w1(const float* __restrict__ MW) {
    int warp = blockIdx.x * 8 + (threadIdx.x >> 5);   // 0..127
    int lane = threadIdx.x & 31;
    const float* row = MW + (size_t)warp * HH;
    float acc = 0.f;
#pragma unroll 4
    for (int k = lane; k < HH; k += 32) acc = fmaf(row[k], g_h1[k], acc);
#pragma unroll
    for (int o = 16; o > 0; o >>= 1) acc += __shfl_xor_sync(0xffffffffu, acc, o);
    if (lane == 0) g_w1[warp] = acc;
}
// which==0: partials of h1 @ R_top -> g_b2p ; which==1: mb @ R_bot -> g_b3p
__global__ __launch_bounds__(256) void k0_bias2a(const float* __restrict__ R,
                                                 const float* __restrict__ mb,
                                                 int which) {
    int id = blockIdx.x * 256 + threadIdx.x;  // 16384
    int n  = id & (FOURH - 1);
    int ch = id >> 11;                        // 0..7
    const float* hp = (which ? mb : g_h1) + ch * 64;
    const float* rp = R + (size_t)(which * HH + ch * 64) * FOURH + n;
    float acc = 0.f;
#pragma unroll 8
    for (int k = 0; k < 64; k++) acc = fmaf(hp[k], rp[(size_t)k * FOURH], acc);
    (which ? g_b3p : g_b2p)[ch * FOURH + n] = acc;
}
__global__ __launch_bounds__(256) void k0_bias2b(const float* __restrict__ rb) {
    int n = blockIdx.x * 256 + threadIdx.x;   // 2048
    float b3 = rb[n];
#pragma unroll
    for (int c = 0; c < 8; c++) b3 += g_b3p[c * FOURH + n];
    g_bias3[n] = b3;
    float b2 = b3;
#pragma unroll
    for (int c = 0; c < 8; c++) b2 += g_b2p[c * FOURH + n];
    g_bias2[n] = b2;
}

// ---------------- Kconv_R: R fp32 -> R^T hi/lo bf16 into g_bhi cols [0,1024)
__global__ __launch_bounds__(256) void kconv_R(const float* __restrict__ R) {
    __shared__ float tile[32][33];
    int k0 = blockIdx.x * 32, n0 = blockIdx.y * 32;
    int tx = threadIdx.x & 31, ty = threadIdx.x >> 5;  // 32 x 8
#pragma unroll
    for (int i = ty; i < 32; i += 8)
        tile[i][tx] = R[(size_t)(k0 + i) * FOURH + n0 + tx];
    __syncthreads();
#pragma unroll
    for (int i = ty; i < 32; i += 8) {
        float v = tile[tx][i];                 // = R[k0+tx][n0+i]
        __nv_bfloat16 hi = __float2bfloat16(v);
        size_t o = (size_t)(n0 + i) * TWOH + k0 + tx;
        g_bhi[o] = hi;
        g_blo[o] = __float2bfloat16(v - __bfloat162float(hi));
    }
}

// ---------------- Kconv_MW: MW fp32 -> bf16 hi/lo (direct + transposed) ----
__global__ __launch_bounds__(256) void kconv_MW(const float* __restrict__ MW) {
    __shared__ float tile[32][33];
    int h0 = blockIdx.x * 32, f0 = blockIdx.y * 32;
    int tx = threadIdx.x & 31, ty = threadIdx.x >> 5;
#pragma unroll
    for (int i = ty; i < 32; i += 8) {
        float v = MW[(size_t)(f0 + i) * HH + h0 + tx];
        tile[i][tx] = v;
        __nv_bfloat16 hi = __float2bfloat16(v);
        size_t o = (size_t)(f0 + i) * HH + h0 + tx;
        g_mwhi[o] = hi;
        g_mwlo[o] = __float2bfloat16(v - __bfloat162float(hi));
    }
    __syncthreads();
#pragma unroll
    for (int i = ty; i < 32; i += 8) {
        float v = tile[tx][i];                 // = MW[f0+tx][h0+i]
        __nv_bfloat16 hi = __float2bfloat16(v);
        size_t o = (size_t)(h0 + i) * FF + f0 + tx;
        g_mthi[o] = hi;
        g_mtlo[o] = __float2bfloat16(v - __bfloat162float(hi));
    }
}

// ---------------- kcopyC: g_chi/g_clo -> g_bhi/g_blo cols [512,640) --------
__global__ __launch_bounds__(256) void kcopyC() {
    int i = blockIdx.x * 256 + threadIdx.x;   // < 2048*128
    int n = i >> 7, f = i & 127;
    size_t d = (size_t)n * TWOH + HH + f;
    g_bhi[d] = g_chi[i];
    g_blo[d] = g_clo[i];
}

// ---------------- K1: LSTM gates (+ emits bf16 hi/lo of h) -----------------
__global__ __launch_bounds__(256) void k1_gates(float* __restrict__ out) {
    int i  = blockIdx.x * 256 + threadIdx.x;
    int hh = i & (HH - 1);
    int g  = i >> 9;
    const float* zr = g_z + (size_t)g * FOURH;
    float zi = zr[hh], zf = zr[HH + hh], zc = zr[2 * HH + hh], zo = zr[3 * HH + hh];
    float c = hsig(zf) * g_c[i] + hsig(zi) * tanhf(zc);
    g_c[i] = c;
    float h = hsig(zo) * tanhf(c);
    size_t o = (size_t)g * TWOH + hh;
    out[o] = h;
    __nv_bfloat16 hi = __float2bfloat16(h);
    g_ahi[o] = hi;
    g_alo[o] = __float2bfloat16(h - __bfloat162float(hi));
}

// ---------------- K3: per-segment softmax + weighted feature sum -----------
// v2 (verified); s hi/lo written into g_ahi/g_alo cols [512,640).
__global__ __launch_bounds__(256) void k3_seg(const float* __restrict__ feat,
                                              const float* __restrict__ wts,
                                              int use_w1) {
    int g = blockIdx.x;
    int tid = threadIdx.x;
    __shared__ __align__(16) float fs[NPS][FF + 4];
    __shared__ float ws[FF];
    __shared__ float as[NPS];
    __shared__ float red[16];
    __shared__ float red2[FF];

    const float* fp = feat + (size_t)g * NPS * FF;
    uint32_t sb;
    asm("{ .reg .u64 t; cvta.to.shared.u64 t, %1; cvt.u32.u64 %0, t; }"
        : "=r"(sb) : "l"((const void*)fs));
#pragma unroll
    for (int i = 0; i < 8; i++) {
        int idx = tid + (i << 8);             // 0..2047
        int node = idx >> 5;
        int col  = (idx & 31) << 2;
        uint32_t dst = sb + (uint32_t)(node * (FF + 4) + col) * 4;
        asm volatile("cp.async.cg.shared.global [%0], [%1], 16;"
                     :: "r"(dst), "l"(fp + (size_t)idx * 4) : "memory");
    }
    asm volatile("cp.async.commit_group;" ::: "memory");
    if (tid < FF) {
        const float* wp = use_w1 ? g_w1 : (g_w + (size_t)g * FF);
        ws[tid] = wp[tid];
    }
    asm volatile("cp.async.wait_group 0;" ::: "memory");
    __syncthreads();

    float e = -1e30f;
    if (tid < NPS) {
        float acc = 0.f;
#pragma unroll
        for (int f = 0; f < FF; f += 4) {
            float4 fv = *(const float4*)&fs[tid][f];
            float4 wv = *(const float4*)&ws[f];
            acc = fmaf(fv.x, wv.x, acc); acc = fmaf(fv.y, wv.y, acc);
            acc = fmaf(fv.z, wv.z, acc); acc = fmaf(fv.w, wv.w, acc);
        }
        e = acc;
    }
    float mx = e;
#pragma unroll
    for (int o = 16; o > 0; o >>= 1) mx = fmaxf(mx, __shfl_xor_sync(0xffffffffu, mx, o));
    if ((tid & 31) == 0) red[tid >> 5] = mx;
    __syncthreads();
    mx = fmaxf(fmaxf(red[0], red[1]), -1e30f);

    float ex = 0.f;
    if (tid < NPS) ex = __expf(e - mx) * wts[(size_t)g * NPS + tid];
    float sm = ex;
#pragma unroll
    for (int o = 16; o > 0; o >>= 1) sm += __shfl_xor_sync(0xffffffffu, sm, o);
    if ((tid & 31) == 0) red[8 + (tid >> 5)] = sm;
    __syncthreads();
    sm = red[8] + red[9];
    if (tid < NPS) as[tid] = ex / sm;
    __syncthreads();

    int col  = tid & (FF - 1);
    int half = tid >> 7;
    int nb   = half << 5;
    float acc = 0.f;
#pragma unroll 16
    for (int n = 0; n < 32; n++) acc = fmaf(as[nb + n], fs[nb + n][col], acc);
    if (half) red2[col] = acc;
    __syncthreads();
    if (!half) {
        float v = acc + red2[col];
        size_t o = (size_t)g * TWOH + HH + col;   // s -> A cols [512,640)
        __nv_bfloat16 hi = __float2bfloat16(v);
        g_ahi[o] = hi;
        g_alo[o] = __float2bfloat16(v - __bfloat162float(hi));
    }
}

// ---------------- KG: generic bf16 hi/lo split mma GEMM --------------------
// C[M,N] = A[M,K] @ B^T[N,K] (+bias) via 3 bf16 products.
// BM=32*MT, BN=128, BK=16, 8 warps, 3-stage cp.async pipeline (dyn smem),
// ldmatrix.x4 fragment loads.  (round-13 verified hot loop)
// ASRC: 0=g_ahi/g_alo  1=g_bhi/g_blo
// BSRC: 0=g_bhi/g_blo  1=g_mwhi/g_mwlo  2=g_mthi/g_mtlo
// OUTSEL: 0 = g_z + (use_b2 ? g_bias2 : g_bias3)
//         1 = g_w (no bias)
//         2 = outp[:,H:] + bias (fp32 only)
//         3 = g_chi/g_clo (bf16 hi/lo only)
#define LDSR 24                        // 16 + 8 pad (bf16); row = 48B
#define MATE (128 * LDSR)
#define STGE (4 * MATE)
#define KG_DSM (3 * STGE * 2)          // 73728 bytes

template <int MT, int ASRC, int BSRC, int LDA, int LDB, int OUTSEL>
__global__ __launch_bounds__(256, 2) void kg_mma(
    int aoff, int boff, int K, float* __restrict__ outp,
    const float* __restrict__ bias, int use_b2)
{
    const __nv_bfloat16* __restrict__ Ahi = (ASRC == 0 ? g_ahi : g_bhi) + aoff;
    const __nv_bfloat16* __restrict__ Alo = (ASRC == 0 ? g_alo : g_blo) + aoff;
    const __nv_bfloat16* __restrict__ Bhi =
        (BSRC == 0 ? g_bhi : BSRC == 1 ? g_mwhi : g_mthi) + boff;
    const __nv_bfloat16* __restrict__ Blo =
        (BSRC == 0 ? g_blo : BSRC == 1 ? g_mwlo : g_mtlo) + boff;

    extern __shared__ __align__(16) __nv_bfloat16 smem[];   // 3 stages
    int tid = threadIdx.x;
    int lane = tid & 31, wid = tid >> 5;
    int wm = wid >> 2, wn = wid & 3;          // 2 x 4 warp grid
    int nblk = blockIdx.x << 7;
    int mblk = blockIdx.y * (32 * MT);
    int g8 = lane >> 2;
    int t2 = (lane & 3) << 1;

    int sr = tid >> 1;
    int sc = (tid & 1) << 3;
    uint32_t sbase;
    asm("{ .reg .u64 t; cvta.to.shared.u64 t, %1; cvt.u32.u64 %0, t; }"
        : "=r"(sbase) : "l"((const void*)smem));
    uint32_t soff = (uint32_t)(sr * LDSR + sc) * 2;

    uint32_t a_lm = (uint32_t)(((wm * (MT * 16)) + (lane & 15)) * LDSR +
                               ((lane >> 4) << 3)) * 2;
    uint32_t b_lm = (uint32_t)(2 * MATE +
                               ((wn * 32) + (((lane >> 3) >> 1) << 3) + (lane & 7)) * LDSR +
                               (((lane >> 3) & 1) << 3)) * 2;

    float acc[MT][4][4];
#pragma unroll
    for (int a = 0; a < MT; a++)
#pragma unroll
        for (int b = 0; b < 4; b++)
#pragma unroll
            for (int c = 0; c < 4; c++) acc[a][b][c] = 0.f;

    int nch = K >> 4;

#define LOAD_STAGE(T, ST) do {                                                  \
    int kg_ = (T) << 4;                                                         \
    uint32_t sb_ = sbase + (uint32_t)(ST) * (STGE * 2) + soff;                  \
    const __nv_bfloat16* b_ = Bhi + (size_t)(nblk + sr) * LDB + kg_ + sc;       \
    if (sr < 32 * MT) {                                                         \
        const __nv_bfloat16* a_ = Ahi + (size_t)(mblk + sr) * LDA + kg_ + sc;   \
        asm volatile("cp.async.cg.shared.global [%0], [%1], 16;"                \
                     :: "r"(sb_), "l"(a_) : "memory");                          \
        asm volatile("cp.async.cg.shared.global [%0], [%1], 16;"                \
                     :: "r"(sb_ + MATE * 2), "l"(Alo + (a_ - Ahi)) : "memory"); \
    }                                                                           \
    asm volatile("cp.async.cg.shared.global [%0], [%1], 16;"                    \
                 :: "r"(sb_ + 2 * MATE * 2), "l"(b_) : "memory");               \
    asm volatile("cp.async.cg.shared.global [%0], [%1], 16;"                    \
                 :: "r"(sb_ + 3 * MATE * 2), "l"(Blo + (b_ - Bhi)) : "memory"); \
    asm volatile("cp.async.commit_group;" ::: "memory");                       \
} while (0)

#define LDSM_X4(r0, r1, r2, r3, addr)                                           \
    asm volatile("ldmatrix.sync.aligned.m8n8.x4.shared.b16 {%0,%1,%2,%3}, [%4];"\
        : "=r"(r0), "=r"(r1), "=r"(r2), "=r"(r3) : "r"(addr) : "memory")

    LOAD_STAGE(0, 0);
    LOAD_STAGE(1, 1);
    asm volatile("cp.async.wait_group 1;" ::: "memory");
    __syncthreads();

    int st = 0;                                // stage of chunk t
    for (int t = 0; t < nch; t++) {
        if (t + 2 < nch) {
            int st2 = st + 2;
            if (st2 >= 3) st2 -= 3;
            LOAD_STAGE(t + 2, st2);
        }

        uint32_t sb = sbase + (uint32_t)st * (STGE * 2);
        uint32_t bh[4][2], bl[4][2];
#pragma unroll
        for (int p = 0; p < 2; p++) {
            uint32_t ba = sb + b_lm + (uint32_t)(p * 16 * LDSR) * 2;
            LDSM_X4(bh[2 * p][0], bh[2 * p][1], bh[2 * p + 1][0], bh[2 * p + 1][1], ba);
            LDSM_X4(bl[2 * p][0], bl[2 * p][1], bl[2 * p + 1][0], bl[2 * p + 1][1],
                    ba + (uint32_t)(MATE * 2));
        }
#pragma unroll
        for (int mt = 0; mt < MT; mt++) {
            uint32_t aa = sb + a_lm + (uint32_t)(mt * 16 * LDSR) * 2;
            uint32_t ahf[4], alf[4];
            LDSM_X4(ahf[0], ahf[1], ahf[2], ahf[3], aa);
            LDSM_X4(alf[0], alf[1], alf[2], alf[3], aa + (uint32_t)(MATE * 2));
#pragma unroll
            for (int nt = 0; nt < 4; nt++) {
                mma16816(acc[mt][nt], ahf, bh[nt]);
                mma16816(acc[mt][nt], ahf, bl[nt]);
                mma16816(acc[mt][nt], alf, bh[nt]);
            }
        }

        if (t + 1 < nch) {
            if (t + 2 < nch) {
                asm volatile("cp.async.wait_group 1;" ::: "memory");
            } else {
                asm volatile("cp.async.wait_group 0;" ::: "memory");
            }
            __syncthreads();
        }
        if (++st == 3) st = 0;
    }
#undef LOAD_STAGE
#undef LDSM_X4

    // ---- epilogue
#pragma unroll
    for (int mt = 0; mt < MT; mt++) {
#pragma unroll
        for (int nt = 0; nt < 4; nt++) {
            int m = mblk + wm * (MT * 16) + mt * 16 + g8;
            int n = nblk + wn * 32 + nt * 8 + t2;
            if (OUTSEL == 0) {
                const float* bp = use_b2 ? g_bias2 : g_bias3;
                float b0 = bp[n], b1 = bp[n + 1];
                float2 v0 = make_float2(acc[mt][nt][0] + b0, acc[mt][nt][1] + b1);
                float2 v1 = make_float2(acc[mt][nt][2] + b0, acc[mt][nt][3] + b1);
                *(float2*)(g_z + (size_t)m * FOURH + n) = v0;
                *(float2*)(g_z + (size_t)(m + 8) * FOURH + n) = v1;
            } else if (OUTSEL == 1) {
                float2 v0 = make_float2(acc[mt][nt][0], acc[mt][nt][1]);
                float2 v1 = make_float2(acc[mt][nt][2], acc[mt][nt][3]);
                *(float2*)(g_w + (size_t)m * FF + n) = v0;
                *(float2*)(g_w + (size_t)(m + 8) * FF + n) = v1;
            } else if (OUTSEL == 2) {
                float b0 = bias[n], b1 = bias[n + 1];
                float2 v0 = make_float2(acc[mt][nt][0] + b0, acc[mt][nt][1] + b1);
                float2 v1 = make_float2(acc[mt][nt][2] + b0, acc[mt][nt][3] + b1);
                *(float2*)(outp + (size_t)m * TWOH + HH + n) = v0;
                *(float2*)(outp + (size_t)(m + 8) * TWOH + HH + n) = v1;
            } else {
                size_t o0 = (size_t)m * FF + n;
                size_t o1 = (size_t)(m + 8) * FF + n;
                float v00 = acc[mt][nt][0], v01 = acc[mt][nt][1];
                float v10 = acc[mt][nt][2], v11 = acc[mt][nt][3];
                __nv_bfloat16 h0 = __float2bfloat16(v00);
                __nv_bfloat16 h1 = __float2bfloat16(v01);
                __nv_bfloat16 h2 = __float2bfloat16(v10);
                __nv_bfloat16 h3 = __float2bfloat16(v11);
                *(__nv_bfloat162*)(g_chi + o0) = __nv_bfloat162{h0, h1};
                *(__nv_bfloat162*)(g_chi + o1) = __nv_bfloat162{h2, h3};
                *(__nv_bfloat162*)(g_clo + o0) = __nv_bfloat162{
                    __float2bfloat16(v00 - __bfloat162float(h0)),
                    __float2bfloat16(v01 - __bfloat162float(h1))};
                *(__nv_bfloat162*)(g_clo + o1) = __nv_bfloat162{
                    __float2bfloat16(v10 - __bfloat162float(h2)),
                    __float2bfloat16(v11 - __bfloat162float(h3))};
            }
        }
    }
}

// ---------------- launch ----------------------------------------------------
extern "C" void kernel_launch(void* const* d_in, const int* in_sizes, int n_in,
                              void* d_out, int out_size) {
    const float* feat = (const float*)d_in[0];   // features (1, N, F)
    const float* wts  = (const float*)d_in[1];   // weights  (1, N)
    const float* MW   = (const float*)d_in[3];   // m_weight (F, H)
    const float* mb   = (const float*)d_in[4];   // m_bias   (H,)
    const float* R    = (const float*)d_in[5];   // recurrent_kernel (2H, 4H)
    const float* rb   = (const float*)d_in[6];   // recurrent_bias   (4H,)
    float* out = (float*)d_out;                  // q_star (1, G, 2H)

    cudaFuncSetAttribute(kg_mma<4, 0, 0, TWOH, TWOH, 0>,
                         cudaFuncAttributeMaxDynamicSharedMemorySize, KG_DSM);
    cudaFuncSetAttribute(kg_mma<1, 0, 1, TWOH, HH, 1>,
                         cudaFuncAttributeMaxDynamicSharedMemorySize, KG_DSM);
    cudaFuncSetAttribute(kg_mma<2, 0, 2, TWOH, FF, 2>,
                         cudaFuncAttributeMaxDynamicSharedMemorySize, KG_DSM);
    cudaFuncSetAttribute(kg_mma<2, 1, 1, TWOH, HH, 3>,
                         cudaFuncAttributeMaxDynamicSharedMemorySize, KG_DSM);

    // ---- prologue
    k0_init <<<1, HH>>>(rb);
    k0_w1   <<<16, 256>>>(MW);
    kconv_MW<<<dim3(HH / 32, FF / 32), 256>>>(MW);
    kconv_R <<<dim3(TWOH / 32, FOURH / 32), 256>>>(R);
    // C^T = (MW @ R_bot)^T : A = R^T rows n, cols [512,1024); B = MW [f][j]
    kg_mma<2, 1, 1, TWOH, HH, 3><<<dim3(1, FOURH / 64), 256, KG_DSM>>>(
        HH, 0, HH, out, rb, 0);
    kcopyC  <<<(FOURH * FF) / 256, 256>>>();
    k3_seg  <<<GG, 256>>>(feat, wts, 1);         // s1 -> A cols [512,640)
    k0_bcast<<<(GG * HH) / 256, 256>>>();
    k0_bias2a<<<64, 256>>>(R, mb, 0);            // h1 @ R_top
    k0_bias2a<<<64, 256>>>(R, mb, 1);            // mb @ R_bot
    k0_bias2b<<<FOURH / 256, 256>>>(rb);

    // ---- iteration 2: z = s1 @ C + bias2   (K = 128)
    kg_mma<4, 0, 0, TWOH, TWOH, 0><<<dim3(FOURH / 128, GG / 128), 256, KG_DSM>>>(
        HH, HH, FF, out, rb, 1);
    k1_gates<<<(GG * HH) / 256, 256>>>(out);     // h2
    kg_mma<1, 0, 1, TWOH, HH, 1><<<dim3(FF / 128, GG / 32), 256, KG_DSM>>>(
        0, 0, HH, out, rb, 0);                   // w2
    k3_seg  <<<GG, 256>>>(feat, wts, 0);         // s2

    // ---- iteration 3: z = [h2|s2] @ [R_top^T|C^T]^T + bias3  (K = 640)
    kg_mma<4, 0, 0, TWOH, TWOH, 0><<<dim3(FOURH / 128, GG / 128), 256, KG_DSM>>>(
        0, 0, HH + FF, out, rb, 0);
    k1_gates<<<(GG * HH) / 256, 256>>>(out);     // h3 -> out[:, :H]
    kg_mma<1, 0, 1, TWOH, HH, 1><<<dim3(FF / 128, GG / 32), 256, KG_DSM>>>(
        0, 0, HH, out, rb, 0);                   // w3
    k3_seg  <<<GG, 256>>>(feat, wts, 0);         // s3
    // r3 = s3 @ MW + mb -> out[:, H:]
    kg_mma<2, 0, 2, TWOH, FF, 2><<<dim3(HH / 128, GG / 64), 256, KG_DSM>>>(
        HH, 0, FF, out, mb, 0);
}